// round 1
// baseline (speedup 1.0000x reference)
#include <cuda_runtime.h>

#define Bb 8
#define Nn 1024
#define Ee 512
#define Hh 8
#define Dd 64
#define NEGV -1000000000.0f

// Scratch (device globals: allocation-free per harness rules)
__device__ float g_q[Bb*Hh*Nn*Dd];
__device__ float g_k[Bb*Hh*Nn*Dd];
__device__ float g_v[Bb*Hh*Nn*Dd];
__device__ float g_attn[Bb*Hh*Nn*Dd];
__device__ unsigned char g_code[Bb*Nn*Nn];

// ---------------------------------------------------------------------------
// Mask precompute: code[b,i,j] = smallest head index that attends.
// head h attends iff dist < thr[h] (thr ascending) -> attend iff h >= count(d>=thr)
// padding mask==0  -> 255 (no head attends)
// i==0 || j==0     -> 0   (all heads attend; padding still wins)
// ---------------------------------------------------------------------------
__device__ __forceinline__ unsigned char code_one(float d, int mk, int i, int j) {
    if (mk == 0) return (unsigned char)255;
    if (i == 0 || j == 0) return (unsigned char)0;
    unsigned char c = 0;
    c += (d >= 0.2f); c += (d >= 0.3f); c += (d >= 0.4f); c += (d >= 0.5f);
    c += (d >= 0.6f); c += (d >= 0.7f); c += (d >= 0.8f); c += (d >= 0.9f);
    return c;
}

__global__ __launch_bounds__(256) void code_kernel(const float* __restrict__ dist,
                                                   const int* __restrict__ mask) {
    int t = blockIdx.x * blockDim.x + threadIdx.x;   // one thread = 4 elements
    int base = t * 4;                                 // < 8*1024*1024
    int rem = base & (Nn*Nn - 1);
    int i = rem >> 10;
    int j0 = rem & (Nn - 1);
    float4 dv = *(const float4*)(dist + base);
    int4  mv = *(const int4*)(mask + base);
    uchar4 o;
    o.x = code_one(dv.x, mv.x, i, j0 + 0);
    o.y = code_one(dv.y, mv.y, i, j0 + 1);
    o.z = code_one(dv.z, mv.z, i, j0 + 2);
    o.w = code_one(dv.w, mv.w, i, j0 + 3);
    *(uchar4*)(g_code + base) = o;
}

// ---------------------------------------------------------------------------
// Q/K/V projection GEMM: out[b,h,n,d] = X[b,n,:] . W[h*64+d,:] + bias
// 64x64 tile, K-tile 16, 256 threads (16x16), 4x4 per thread.
// ---------------------------------------------------------------------------
__global__ __launch_bounds__(256) void proj_kernel(
    const float* __restrict__ Xq, const float* __restrict__ Xk, const float* __restrict__ Xv,
    const float* __restrict__ Wq, const float* __restrict__ bq,
    const float* __restrict__ Wk, const float* __restrict__ bk,
    const float* __restrict__ Wv, const float* __restrict__ bv)
{
    __shared__ float Xs[16][68];
    __shared__ float Ws[16][68];

    int which = blockIdx.z;
    const float* X    = (which == 0) ? Xq : (which == 1) ? Xk : Xv;
    const float* W    = (which == 0) ? Wq : (which == 1) ? Wk : Wv;
    const float* bias = (which == 0) ? bq : (which == 1) ? bk : bv;
    float* out        = (which == 0) ? g_q : (which == 1) ? g_k : g_v;

    int m0 = blockIdx.x * 64;         // over B*N = 8192
    int c0 = blockIdx.y * 64;         // over E = 512
    int tid = threadIdx.x;
    int ty = tid >> 4, tx = tid & 15;
    int row = tid >> 2, seg = tid & 3;

    const float* Xp = X + (m0 + row) * Ee + seg * 4;
    const float* Wp = W + (c0 + row) * Ee + seg * 4;

    float acc[4][4] = {};

    for (int kt = 0; kt < Ee / 16; kt++) {
        float4 xv = *(const float4*)(Xp + kt * 16);
        float4 wv = *(const float4*)(Wp + kt * 16);
        __syncthreads();
        int kk = seg * 4;
        Xs[kk+0][row] = xv.x; Xs[kk+1][row] = xv.y; Xs[kk+2][row] = xv.z; Xs[kk+3][row] = xv.w;
        Ws[kk+0][row] = wv.x; Ws[kk+1][row] = wv.y; Ws[kk+2][row] = wv.z; Ws[kk+3][row] = wv.w;
        __syncthreads();
        #pragma unroll
        for (int k = 0; k < 16; k++) {
            float a[4], b4[4];
            *(float4*)a  = *(const float4*)(&Xs[k][ty * 4]);
            *(float4*)b4 = *(const float4*)(&Ws[k][tx * 4]);
            #pragma unroll
            for (int i = 0; i < 4; i++)
                #pragma unroll
                for (int j = 0; j < 4; j++)
                    acc[i][j] += a[i] * b4[j];
        }
    }

    float4 bb = *(const float4*)(bias + c0 + tx * 4);
    int h = c0 >> 6;                 // c0 is a multiple of 64
    int d = tx * 4;
    #pragma unroll
    for (int i = 0; i < 4; i++) {
        int m = m0 + ty * 4 + i;
        int b_ = m >> 10, n = m & (Nn - 1);
        float4 o;
        o.x = acc[i][0] + bb.x; o.y = acc[i][1] + bb.y;
        o.z = acc[i][2] + bb.z; o.w = acc[i][3] + bb.w;
        *(float4*)(out + ((((b_ << 3) + h) << 16) + (n << 6) + d)) = o;
    }
}

// ---------------------------------------------------------------------------
// Flash attention (fp32): per (b,h,row-block of 64). Online softmax over 16
// key tiles of 64. Mask via per-element code byte: attend iff h >= code.
// ---------------------------------------------------------------------------
__global__ __launch_bounds__(256) void flash_kernel() {
    extern __shared__ float sm[];
    float* Qt = sm;                        // [64][68] (d-major)
    float* Kt = sm + 64 * 68;              // [64][68] (d-major)
    float* Vs = sm + 2 * 64 * 68;          // [64][68] (c-major)
    float* Pt = sm + 3 * 64 * 68;          // [64][68] (c-major)
    unsigned char* Cs = (unsigned char*)(sm + 4 * 64 * 68);  // [64][64]

    int rb = blockIdx.x, h = blockIdx.y, b = blockIdx.z;
    const float* Qg = g_q + (((b * Hh + h) * Nn + rb * 64) * Dd);
    const float* Kg = g_k + ((b * Hh + h) * Nn) * Dd;
    const float* Vg = g_v + ((b * Hh + h) * Nn) * Dd;
    const unsigned char* code = g_code + (b * Nn + rb * 64) * Nn;

    int tid = threadIdx.x;
    int ty = tid >> 4, tx = tid & 15;

    // load Q transposed (Qt[d][r])
    #pragma unroll
    for (int l = 0; l < 4; l++) {
        int idx = tid + l * 256;
        int r = idx >> 4;
        int d0 = (idx & 15) << 2;
        float4 q4 = *(const float4*)(Qg + r * 64 + d0);
        Qt[(d0+0)*68 + r] = q4.x;
        Qt[(d0+1)*68 + r] = q4.y;
        Qt[(d0+2)*68 + r] = q4.z;
        Qt[(d0+3)*68 + r] = q4.w;
    }

    float acc[4][4] = {};
    float m_i[4], l_i[4];
    #pragma unroll
    for (int i = 0; i < 4; i++) { m_i[i] = -1e30f; l_i[i] = 0.0f; }

    for (int kb = 0; kb < Nn / 64; kb++) {
        __syncthreads();   // prior PV-GEMM done before Kt/Vs/Cs overwrite
        #pragma unroll
        for (int l = 0; l < 4; l++) {
            int idx = tid + l * 256;
            int c = idx >> 4;
            int d0 = (idx & 15) << 2;
            float4 k4 = *(const float4*)(Kg + (kb * 64 + c) * 64 + d0);
            Kt[(d0+0)*68 + c] = k4.x;
            Kt[(d0+1)*68 + c] = k4.y;
            Kt[(d0+2)*68 + c] = k4.z;
            Kt[(d0+3)*68 + c] = k4.w;
            float4 v4 = *(const float4*)(Vg + (kb * 64 + c) * 64 + d0);
            *(float4*)(Vs + c * 68 + d0) = v4;
        }
        {
            int r = tid >> 2;
            int s4 = (tid & 3) << 4;
            *(uint4*)(Cs + r * 64 + s4) = *(const uint4*)(code + r * Nn + kb * 64 + s4);
        }
        __syncthreads();

        // S = Q . K^T
        float s[4][4] = {};
        #pragma unroll
        for (int d = 0; d < 64; d++) {
            float a[4], b4[4];
            *(float4*)a  = *(const float4*)(Qt + d * 68 + ty * 4);
            *(float4*)b4 = *(const float4*)(Kt + d * 68 + tx * 4);
            #pragma unroll
            for (int i = 0; i < 4; i++)
                #pragma unroll
                for (int j = 0; j < 4; j++)
                    s[i][j] += a[i] * b4[j];
        }

        // scale + mask
        #pragma unroll
        for (int i = 0; i < 4; i++)
            #pragma unroll
            for (int j = 0; j < 4; j++) {
                unsigned int cd = Cs[(ty * 4 + i) * 64 + tx * 4 + j];
                s[i][j] = ((unsigned int)h >= cd) ? s[i][j] * 0.125f : NEGV;
            }

        // online softmax
        float rm[4], corr[4], ps[4];
        #pragma unroll
        for (int i = 0; i < 4; i++) {
            float r = fmaxf(fmaxf(s[i][0], s[i][1]), fmaxf(s[i][2], s[i][3]));
            #pragma unroll
            for (int o = 8; o > 0; o >>= 1)
                r = fmaxf(r, __shfl_xor_sync(0xffffffffu, r, o));
            rm[i] = r;
            float mn = fmaxf(m_i[i], rm[i]);
            corr[i] = __expf(m_i[i] - mn);
            m_i[i] = mn;
            ps[i] = 0.0f;
        }
        #pragma unroll
        for (int i = 0; i < 4; i++)
            #pragma unroll
            for (int j = 0; j < 4; j++) {
                float p = __expf(s[i][j] - m_i[i]);
                ps[i] += p;
                Pt[(tx * 4 + j) * 68 + (ty * 4 + i)] = p;
            }
        #pragma unroll
        for (int i = 0; i < 4; i++) {
            float r = ps[i];
            #pragma unroll
            for (int o = 8; o > 0; o >>= 1)
                r += __shfl_xor_sync(0xffffffffu, r, o);
            l_i[i] = l_i[i] * corr[i] + r;
            #pragma unroll
            for (int j = 0; j < 4; j++) acc[i][j] *= corr[i];
        }
        __syncthreads();

        // O += P . V
        #pragma unroll
        for (int c = 0; c < 64; c++) {
            float a[4], v4[4];
            *(float4*)a  = *(const float4*)(Pt + c * 68 + ty * 4);
            *(float4*)v4 = *(const float4*)(Vs + c * 68 + tx * 4);
            #pragma unroll
            for (int i = 0; i < 4; i++)
                #pragma unroll
                for (int j = 0; j < 4; j++)
                    acc[i][j] += a[i] * v4[j];
        }
    }

    float* Og = g_attn + (((b * Hh + h) * Nn + rb * 64) * Dd);
    #pragma unroll
    for (int i = 0; i < 4; i++) {
        float inv = 1.0f / l_i[i];
        float4 o;
        o.x = acc[i][0] * inv; o.y = acc[i][1] * inv;
        o.z = acc[i][2] * inv; o.w = acc[i][3] * inv;
        *(float4*)(Og + (ty * 4 + i) * 64 + tx * 4) = o;
    }
}

// ---------------------------------------------------------------------------
// Output projection: y[m, co] = attn_flat[m, :] . Wo[co, :] + bo
// attn_flat[m, c] gathered from g_attn[b,h,n,d] with m=(b,n), c=(h,d)
// ---------------------------------------------------------------------------
__global__ __launch_bounds__(256) void oproj_kernel(const float* __restrict__ W,
                                                    const float* __restrict__ bias,
                                                    float* __restrict__ out) {
    __shared__ float Xs[16][68];
    __shared__ float Ws[16][68];

    int m0 = blockIdx.x * 64;
    int c0 = blockIdx.y * 64;
    int tid = threadIdx.x;
    int ty = tid >> 4, tx = tid & 15;
    int row = tid >> 2, seg = tid & 3;

    int m = m0 + row;
    int b_ = m >> 10, n = m & (Nn - 1);
    const float* Wp = W + (c0 + row) * Ee + seg * 4;

    float acc[4][4] = {};

    for (int kt = 0; kt < Ee / 16; kt++) {
        int k0 = kt * 16;
        int hh = k0 >> 6;
        int dd = (k0 & 63) + seg * 4;
        float4 xv = *(const float4*)(g_attn + ((((b_ << 3) + hh) << 16) + (n << 6) + dd));
        float4 wv = *(const float4*)(Wp + k0);
        __syncthreads();
        int kk = seg * 4;
        Xs[kk+0][row] = xv.x; Xs[kk+1][row] = xv.y; Xs[kk+2][row] = xv.z; Xs[kk+3][row] = xv.w;
        Ws[kk+0][row] = wv.x; Ws[kk+1][row] = wv.y; Ws[kk+2][row] = wv.z; Ws[kk+3][row] = wv.w;
        __syncthreads();
        #pragma unroll
        for (int k = 0; k < 16; k++) {
            float a[4], b4[4];
            *(float4*)a  = *(const float4*)(&Xs[k][ty * 4]);
            *(float4*)b4 = *(const float4*)(&Ws[k][tx * 4]);
            #pragma unroll
            for (int i = 0; i < 4; i++)
                #pragma unroll
                for (int j = 0; j < 4; j++)
                    acc[i][j] += a[i] * b4[j];
        }
    }

    float4 bb = *(const float4*)(bias + c0 + tx * 4);
    #pragma unroll
    for (int i = 0; i < 4; i++) {
        int mm = m0 + ty * 4 + i;
        float4 o;
        o.x = acc[i][0] + bb.x; o.y = acc[i][1] + bb.y;
        o.z = acc[i][2] + bb.z; o.w = acc[i][3] + bb.w;
        *(float4*)(out + mm * Ee + c0 + tx * 4) = o;
    }
}

// ---------------------------------------------------------------------------
extern "C" void kernel_launch(void* const* d_in, const int* in_sizes, int n_in,
                              void* d_out, int out_size) {
    const float* query = (const float*)d_in[0];
    const float* key   = (const float*)d_in[1];
    const float* value = (const float*)d_in[2];
    const float* dist  = (const float*)d_in[3];
    const int*   mask  = (const int*)d_in[4];
    const float* Wq = (const float*)d_in[5];
    const float* bq = (const float*)d_in[6];
    const float* Wk = (const float*)d_in[7];
    const float* bk = (const float*)d_in[8];
    const float* Wv = (const float*)d_in[9];
    const float* bv = (const float*)d_in[10];
    const float* Wo = (const float*)d_in[11];
    const float* bo = (const float*)d_in[12];
    float* out = (float*)d_out;

    cudaFuncSetAttribute(flash_kernel, cudaFuncAttributeMaxDynamicSharedMemorySize, 73728);

    // 1) mask code precompute: 8M elems, 4/thread
    code_kernel<<<(Bb * Nn * Nn) / (4 * 256), 256>>>(dist, mask);
    // 2) Q/K/V projections
    proj_kernel<<<dim3((Bb * Nn) / 64, Ee / 64, 3), 256>>>(query, key, value,
                                                           Wq, bq, Wk, bk, Wv, bv);
    // 3) flash attention
    flash_kernel<<<dim3(Nn / 64, Hh, Bb), 256, 73728>>>();
    // 4) output projection
    oproj_kernel<<<dim3((Bb * Nn) / 64, Ee / 64), 256>>>(Wo, bo, out);
}